// round 9
// baseline (speedup 1.0000x reference)
#include <cuda_runtime.h>
#include <cuda_bf16.h>
#include <cstdint>

// Shapes (fixed by the problem): B=8, N=2048, low=512, high=4096
#define Bb 8
#define Nn 2048
#define LO 512
#define HI 4096
#define BIGF 9.0e15f

// ---------------- fp32 scratch --------------------------------------------
__device__ float g_E[Bb*LO*HI];        // raw scores e' (pre-bias/scale)
__device__ float g_s[Bb*LO];
__device__ float g_u[Bb*LO];
__device__ float g_v[Bb*HI];
__device__ float g_w[Bb*HI];
__device__ float g_z[Bb*HI];

// ---------------- bf16 hi/lo operands (K-major) -----------------------------
__device__ __align__(256) __nv_bfloat16 g_XtH[Bb*LO*Nn];   // X^T per batch
__device__ __align__(256) __nv_bfloat16 g_XtL[Bb*LO*Nn];
__device__ __align__(256) __nv_bfloat16 g_XH [Bb*Nn*LO];   // X
__device__ __align__(256) __nv_bfloat16 g_XL [Bb*Nn*LO];
__device__ __align__(256) __nv_bfloat16 g_WqH[LO*LO];
__device__ __align__(256) __nv_bfloat16 g_WqL[LO*LO];
__device__ __align__(256) __nv_bfloat16 g_WkH[HI*LO];
__device__ __align__(256) __nv_bfloat16 g_WkL[HI*LO];
__device__ __align__(256) __nv_bfloat16 g_WvTH[LO*LO];     // Wv^T
__device__ __align__(256) __nv_bfloat16 g_WvTL[LO*LO];
__device__ __align__(256) __nv_bfloat16 g_OH [HI*HI];      // O
__device__ __align__(256) __nv_bfloat16 g_OL [HI*HI];
__device__ __align__(256) __nv_bfloat16 g_GH [Bb*LO*LO];   // X^T X (epilogue split)
__device__ __align__(256) __nv_bfloat16 g_GL [Bb*LO*LO];
__device__ __align__(256) __nv_bfloat16 g_TH [Bb*LO*LO];   // Wq G
__device__ __align__(256) __nv_bfloat16 g_TL [Bb*LO*LO];
__device__ __align__(256) __nv_bfloat16 g_AH [Bb*LO*HI];   // attn weights
__device__ __align__(256) __nv_bfloat16 g_AL [Bb*LO*HI];
__device__ __align__(256) __nv_bfloat16 g_SH [Bb*HI*LO];   // S = O A^T
__device__ __align__(256) __nv_bfloat16 g_SL [Bb*HI*LO];
__device__ __align__(256) __nv_bfloat16 g_RtH[Bb*HI*LO];   // R^T = S Wv
__device__ __align__(256) __nv_bfloat16 g_RtL[Bb*HI*LO];

// ---------------- PTX helpers ----------------------------------------------
__device__ __forceinline__ uint32_t s2u(const void* p) {
    uint32_t a;
    asm("{ .reg .u64 t; cvta.to.shared.u64 t, %1; cvt.u32.u64 %0, t; }" : "=r"(a) : "l"(p));
    return a;
}
#define SWZ(x) ((x) ^ (((x) >> 3) & 0x70))

__device__ __forceinline__ void cp16(uint32_t sa, const void* ga) {
    asm volatile("cp.async.cg.shared.global [%0], [%1], 16;" :: "r"(sa), "l"(ga));
}

__device__ __forceinline__ void ldsm4(uint32_t& r0, uint32_t& r1, uint32_t& r2,
                                      uint32_t& r3, uint32_t a) {
    asm volatile("ldmatrix.sync.aligned.m8n8.x4.shared.b16 {%0,%1,%2,%3}, [%4];"
        : "=r"(r0), "=r"(r1), "=r"(r2), "=r"(r3) : "r"(a));
}

__device__ __forceinline__ void mma16816(float* d, const uint32_t* a,
                                         uint32_t b0, uint32_t b1) {
    asm volatile(
        "mma.sync.aligned.m16n8k16.row.col.f32.bf16.bf16.f32 "
        "{%0,%1,%2,%3}, {%4,%5,%6,%7}, {%8,%9}, {%0,%1,%2,%3};"
        : "+f"(d[0]), "+f"(d[1]), "+f"(d[2]), "+f"(d[3])
        : "r"(a[0]), "r"(a[1]), "r"(a[2]), "r"(a[3]), "r"(b0), "r"(b1));
}

__device__ __forceinline__ __nv_bfloat162 split_pair(float x, float y, __nv_bfloat162& lo) {
    __nv_bfloat16 hx = __float2bfloat16(x);
    __nv_bfloat16 hy = __float2bfloat16(y);
    __nv_bfloat16 lx = __float2bfloat16(x - __bfloat162float(hx));
    __nv_bfloat16 ly = __float2bfloat16(y - __bfloat162float(hy));
    lo = __nv_bfloat162(lx, ly);
    return __nv_bfloat162(hx, hy);
}

// ---------------- HMMA GEMM: C = Ah·Bh^T + Al·Bh^T + Ah·Bl^T ---------------
// CTA tile 128x128, 8 warps (warp tile 32x64), K-chunk 64, 3-stage cp.async.
// Output: fp32 C (+bias) and/or bf16 hi/lo split pair.
#define STAGES 3
#define KCH 64
#define STAGE_T 16384                 // one 128x64 bf16 tile
#define STAGE_BYTES 65536             // Ahi + Alo + Bhi + Blo
#define GEMM_SMEM (STAGES * STAGE_BYTES)   // 196608

__global__ void __launch_bounds__(256) mma_gemm(
    int K,
    const __nv_bfloat16* __restrict__ Ahi, const __nv_bfloat16* __restrict__ Alo, long sA,
    const __nv_bfloat16* __restrict__ Bhi, const __nv_bfloat16* __restrict__ Blo, long sB,
    float* __restrict__ C,
    __nv_bfloat16* __restrict__ Chi, __nv_bfloat16* __restrict__ Clo,
    int ldc, long sC,
    const float* __restrict__ bias, long sBias)
{
    extern __shared__ char smem[];
    const uint32_t sb = s2u(smem);
    const int tid = threadIdx.x;
    const int wid = tid >> 5, lane = tid & 31;
    const int bz = blockIdx.z;
    const int row0 = blockIdx.y * 128;
    const int col0 = blockIdx.x * 128;
    Ahi += (long)bz * sA; Alo += (long)bz * sA;
    Bhi += (long)bz * sB; Blo += (long)bz * sB;

    const int warp_m = (wid & 3) * 32;
    const int warp_n = (wid >> 2) * 64;

    float acc[2][8][4];
#pragma unroll
    for (int mi = 0; mi < 2; mi++)
#pragma unroll
        for (int ni = 0; ni < 8; ni++)
#pragma unroll
            for (int q = 0; q < 4; q++) acc[mi][ni][q] = 0.f;

    const int NC = K / KCH;

    auto load_chunk = [&](int c, int s) {
        uint32_t st = sb + s * STAGE_BYTES;
        long k0 = (long)c * KCH;
#pragma unroll
        for (int i = 0; i < 16; i++) {
            int idx = tid + i * 256;          // 0..4095
            int t = i >> 2;                   // tile 0..3 (compile-time per iter)
            int j = idx & 1023;
            int r = j >> 3, cj = j & 7;
            const __nv_bfloat16* src = (t == 0) ? Ahi : (t == 1) ? Alo
                                     : (t == 2) ? Bhi : Blo;
            int rb = (t < 2) ? row0 : col0;
            cp16(st + t * STAGE_T + SWZ(r * 128 + cj * 16),
                 src + (long)(rb + r) * K + k0 + cj * 8);
        }
    };

    const int lrow = lane & 15;
    const int lcol = (lane >> 4) * 16;

    load_chunk(0, 0);
    asm volatile("cp.async.commit_group;" ::: "memory");
    if (NC > 1) load_chunk(1, 1);
    asm volatile("cp.async.commit_group;" ::: "memory");

    for (int c = 0; c < NC; c++) {
        asm volatile("cp.async.wait_group 1;" ::: "memory");
        __syncthreads();                        // all warps done with chunk c-1
        if (c + 2 < NC) load_chunk(c + 2, (c + 2) % STAGES);
        asm volatile("cp.async.commit_group;" ::: "memory");

        uint32_t st = sb + (c % STAGES) * STAGE_BYTES;
        uint32_t ahb = st, alb = st + STAGE_T;
        uint32_t bhb = st + 2 * STAGE_T, blb = st + 3 * STAGE_T;
#pragma unroll
        for (int ks = 0; ks < 4; ks++) {
            uint32_t afh[2][4], afl[2][4], bfh[8][2], bfl[8][2];
#pragma unroll
            for (int mi = 0; mi < 2; mi++) {
                uint32_t off = SWZ((warp_m + mi * 16 + lrow) * 128 + ks * 32 + lcol);
                ldsm4(afh[mi][0], afh[mi][1], afh[mi][2], afh[mi][3], ahb + off);
                ldsm4(afl[mi][0], afl[mi][1], afl[mi][2], afl[mi][3], alb + off);
            }
#pragma unroll
            for (int nb = 0; nb < 4; nb++) {
                uint32_t off = SWZ((warp_n + nb * 16 + lrow) * 128 + ks * 32 + lcol);
                uint32_t r0, r1, r2, r3;
                ldsm4(r0, r1, r2, r3, bhb + off);
                bfh[2 * nb][0] = r0; bfh[2 * nb][1] = r2;
                bfh[2 * nb + 1][0] = r1; bfh[2 * nb + 1][1] = r3;
                ldsm4(r0, r1, r2, r3, blb + off);
                bfl[2 * nb][0] = r0; bfl[2 * nb][1] = r2;
                bfl[2 * nb + 1][0] = r1; bfl[2 * nb + 1][1] = r3;
            }
#pragma unroll
            for (int mi = 0; mi < 2; mi++)
#pragma unroll
                for (int ni = 0; ni < 8; ni++)
                    mma16816(acc[mi][ni], afh[mi], bfh[ni][0], bfh[ni][1]);
#pragma unroll
            for (int mi = 0; mi < 2; mi++)
#pragma unroll
                for (int ni = 0; ni < 8; ni++)
                    mma16816(acc[mi][ni], afl[mi], bfh[ni][0], bfh[ni][1]);
#pragma unroll
            for (int mi = 0; mi < 2; mi++)
#pragma unroll
                for (int ni = 0; ni < 8; ni++)
                    mma16816(acc[mi][ni], afh[mi], bfl[ni][0], bfl[ni][1]);
        }
    }

    // epilogue: thread holds rows lane/4 (+8), col pairs (lane%4)*2
    const int cbase = col0 + warp_n + (lane & 3) * 2;
#pragma unroll
    for (int mi = 0; mi < 2; mi++) {
#pragma unroll
        for (int h = 0; h < 2; h++) {
            int row = row0 + warp_m + mi * 16 + (lane >> 2) + h * 8;
            long base = (long)bz * sC + (long)row * ldc + cbase;
            if (C) {
                float* cr = C + base;
                if (bias) {
                    const float* bp = bias + bz * sBias + cbase;
#pragma unroll
                    for (int ni = 0; ni < 8; ni++) {
                        float2 v;
                        v.x = acc[mi][ni][h * 2]     + bp[ni * 8];
                        v.y = acc[mi][ni][h * 2 + 1] + bp[ni * 8 + 1];
                        *(float2*)(cr + ni * 8) = v;
                    }
                } else {
#pragma unroll
                    for (int ni = 0; ni < 8; ni++) {
                        float2 v;
                        v.x = acc[mi][ni][h * 2];
                        v.y = acc[mi][ni][h * 2 + 1];
                        *(float2*)(cr + ni * 8) = v;
                    }
                }
            }
            if (Chi) {
#pragma unroll
                for (int ni = 0; ni < 8; ni++) {
                    __nv_bfloat162 lo;
                    __nv_bfloat162 hi = split_pair(acc[mi][ni][h * 2],
                                                   acc[mi][ni][h * 2 + 1], lo);
                    *(__nv_bfloat162*)(Chi + base + ni * 8) = hi;
                    *(__nv_bfloat162*)(Clo + base + ni * 8) = lo;
                }
            }
        }
    }
}

// ---------------- fp32 -> bf16 hi/lo split (same layout, coalesced) ---------
__global__ void split2_kernel(const float* __restrict__ src, long sS,
                              __nv_bfloat16* __restrict__ hi,
                              __nv_bfloat16* __restrict__ lo,
                              long sD, int pairs)
{
    int b = blockIdx.y;
    const float2* s2 = (const float2*)(src + (long)b * sS);
    __nv_bfloat162* h2 = (__nv_bfloat162*)(hi + (long)b * sD);
    __nv_bfloat162* l2 = (__nv_bfloat162*)(lo + (long)b * sD);
    for (int i = blockIdx.x * 256 + threadIdx.x; i < pairs; i += gridDim.x * 256) {
        float2 x = s2[i];
        __nv_bfloat162 lv;
        __nv_bfloat162 hv = split_pair(x.x, x.y, lv);
        h2[i] = hv;
        l2[i] = lv;
    }
}

// transpose + split: src [R,C] -> hi/lo [C,R] (K-major over r)
__global__ void tsplit2_kernel(const float* __restrict__ src, long sS,
                               __nv_bfloat16* __restrict__ hi,
                               __nv_bfloat16* __restrict__ lo,
                               long sD, int R, int C)
{
    __shared__ float t[32][33];
    int b = blockIdx.z;
    src += (long)b * sS;
    int r0 = blockIdx.y * 32, c0 = blockIdx.x * 32;
    int tx = threadIdx.x, ty = threadIdx.y;   // (32, 8)
#pragma unroll
    for (int i = 0; i < 4; i++)
        t[ty + 8 * i][tx] = src[(long)(r0 + ty + 8 * i) * C + c0 + tx];
    __syncthreads();
#pragma unroll
    for (int i = 0; i < 4; i++) {
        int cc = c0 + ty + 8 * i;
        int rr = r0 + tx;
        float x = t[tx][ty + 8 * i];
        __nv_bfloat16 h = __float2bfloat16(x);
        __nv_bfloat16 l = __float2bfloat16(x - __bfloat162float(h));
        long o = (long)b * sD + (long)cc * R + rr;
        hi[o] = h;
        lo[o] = l;
    }
}

// ---------------- small helper kernels --------------------------------------
__device__ __forceinline__ float warpSum(float v) {
#pragma unroll
    for (int o = 16; o; o >>= 1) v += __shfl_xor_sync(0xffffffffu, v, o);
    return v;
}

__global__ void colsum_kernel(const float* __restrict__ X, float* __restrict__ s) {
    int b = blockIdx.x, m = threadIdx.x;
    const float* xb = X + (long)b * Nn * LO;
    float acc = 0.f;
    for (int n = 0; n < Nn; n++) acc += xb[(long)n * LO + m];
    s[b * LO + m] = acc;
}

__global__ void rowdot_kernel(const float* __restrict__ W, const float* __restrict__ x,
                              float* __restrict__ out, int rows, int cols,
                              const float* __restrict__ addv) {
    int warp = threadIdx.x >> 5, lane = threadIdx.x & 31;
    int r = blockIdx.x * 8 + warp;
    int b = blockIdx.y;
    if (r >= rows) return;
    const float* xb = x + (long)b * cols;
    const float* wr = W + (long)r * cols;
    float s = 0.f;
    for (int c = lane; c < cols; c += 32) s += wr[c] * xb[c];
    s = warpSum(s);
    if (lane == 0) out[(long)b * rows + r] = s + (addv ? addv[r] : 0.f);
}

// w[b][h] = sum_l bv[l] * (AH+AL)[b,l,h]
__global__ void wvec_kernel(const __nv_bfloat16* __restrict__ AH,
                            const __nv_bfloat16* __restrict__ AL,
                            const float* __restrict__ bv,
                            float* __restrict__ w) {
    int h = blockIdx.x * 256 + threadIdx.x;
    int b = blockIdx.y;
    const __nv_bfloat16* Ah = AH + (long)b * LO * HI;
    const __nv_bfloat16* Al = AL + (long)b * LO * HI;
    float acc = 0.f;
    for (int l = 0; l < LO; l++) {
        long o = (long)l * HI + h;
        acc += bv[l] * (__bfloat162float(Ah[o]) + __bfloat162float(Al[o]));
    }
    w[(long)b * HI + h] = acc;
}

// ---------------- fused softmax + min-max-norm attention combine ------------
// reads raw scores E, writes attn weights as hi/lo bf16 pair
__global__ void __launch_bounds__(256) attn_kernel(
    const float* __restrict__ E, const int* __restrict__ linkage,
    const float* __restrict__ u, const float* __restrict__ bq,
    const float* __restrict__ v, const float* __restrict__ bk,
    __nv_bfloat16* __restrict__ AH, __nv_bfloat16* __restrict__ AL)
{
    __shared__ float red[8];
    const int l = blockIdx.x, b = blockIdx.y;
    const float* row = E + ((long)(b * LO + l)) * HI;
    const int* lrow = linkage + (long)l * HI;
    const float* vb = v + (long)b * HI;
    const float uval = u[b * LO + l];
    const float bqv  = bq[l];

    float ev[16];
    unsigned mbits = 0;
    float gmax = -3.4e38f, mn = BIGF, mx = -BIGF;

#pragma unroll
    for (int j = 0; j < 16; j++) {
        int hh = threadIdx.x + j * 256;
        float bkh = bk[hh];
        float e = (row[hh] + uval * bkh + bqv * (vb[hh] + (float)Nn * bkh)) * 0.015625f;
        ev[j] = e;
        gmax = fmaxf(gmax, e);
        if (lrow[hh] > 0) {
            mbits |= 1u << j;
            mn = fminf(mn, e);
            mx = fmaxf(mx, e);
        }
    }

    const int wid = threadIdx.x >> 5, lane = threadIdx.x & 31;
#pragma unroll
    for (int o = 16; o; o >>= 1) gmax = fmaxf(gmax, __shfl_xor_sync(0xffffffffu, gmax, o));
    if (lane == 0) red[wid] = gmax;
    __syncthreads();
    gmax = red[0];
#pragma unroll
    for (int i = 1; i < 8; i++) gmax = fmaxf(gmax, red[i]);
    __syncthreads();

#pragma unroll
    for (int o = 16; o; o >>= 1) mn = fminf(mn, __shfl_xor_sync(0xffffffffu, mn, o));
    if (lane == 0) red[wid] = mn;
    __syncthreads();
    mn = red[0];
#pragma unroll
    for (int i = 1; i < 8; i++) mn = fminf(mn, red[i]);
    __syncthreads();

#pragma unroll
    for (int o = 16; o; o >>= 1) mx = fmaxf(mx, __shfl_xor_sync(0xffffffffu, mx, o));
    if (lane == 0) red[wid] = mx;
    __syncthreads();
    mx = red[0];
#pragma unroll
    for (int i = 1; i < 8; i++) mx = fmaxf(mx, red[i]);
    __syncthreads();

    float den = mx - mn;
    if (den == 0.0f) den = 1e-6f;
    const bool hasMask = (mx != -BIGF);
    const float lmax = hasMask ? (((mx - mn) == 0.0f) ? 0.0f : 1.0f) : -BIGF;

    float eg[16], el[16];
    float gsum = 0.f, lsum = 0.f;
#pragma unroll
    for (int j = 0; j < 16; j++) {
        float e = ev[j];
        float g = __expf(e - gmax);
        eg[j] = g;
        gsum += g;
        float lv = ((mbits >> j) & 1) ? (e - mn) / den : -BIGF;
        float ll = __expf(lv - lmax);
        el[j] = ll;
        lsum += ll;
    }

    gsum = warpSum(gsum);
    if (lane == 0) red[wid] = gsum;
    __syncthreads();
    gsum = red[0];
#pragma unroll
    for (int i = 1; i < 8; i++) gsum += red[i];
    __syncthreads();

    lsum = warpSum(lsum);
    if (lane == 0) red[wid] = lsum;
    __syncthreads();
    lsum = red[0];
#pragma unroll
    for (int i = 1; i < 8; i++) lsum += red[i];

    const float rg = 1.0f / gsum, rl = 1.0f / lsum;
    long obase = ((long)(b * LO + l)) * HI;
#pragma unroll
    for (int j = 0; j < 16; j++) {
        int hh = threadIdx.x + j * 256;
        float a = eg[j] * rg + el[j] * rl;
        __nv_bfloat16 ah = __float2bfloat16(a);
        __nv_bfloat16 al = __float2bfloat16(a - __bfloat162float(ah));
        AH[obase + hh] = ah;
        AL[obase + hh] = al;
    }
}

// ---------------- host launch ------------------------------------------------
template <typename T>
static T* symaddr(const void* sym) {
    void* p = nullptr;
    cudaGetSymbolAddress(&p, sym);
    return (T*)p;
}

extern "C" void kernel_launch(void* const* d_in, const int* in_sizes, int n_in,
                              void* d_out, int out_size) {
    const float* X   = (const float*)d_in[0];
    const int*   lk  = (const int*)d_in[1];
    const float* wq  = (const float*)d_in[2];
    const float* bq  = (const float*)d_in[3];
    const float* wk  = (const float*)d_in[4];
    const float* bk  = (const float*)d_in[5];
    const float* wv  = (const float*)d_in[6];
    const float* bv  = (const float*)d_in[7];
    const float* ow  = (const float*)d_in[8];
    const float* ob  = (const float*)d_in[9];
    float* out = (float*)d_out;

    float* E = symaddr<float>(g_E);
    float* s = symaddr<float>(g_s);
    float* u = symaddr<float>(g_u);
    float* v = symaddr<float>(g_v);
    float* w = symaddr<float>(g_w);
    float* z = symaddr<float>(g_z);

    __nv_bfloat16* XtH  = symaddr<__nv_bfloat16>(g_XtH);
    __nv_bfloat16* XtL  = symaddr<__nv_bfloat16>(g_XtL);
    __nv_bfloat16* XH   = symaddr<__nv_bfloat16>(g_XH);
    __nv_bfloat16* XL   = symaddr<__nv_bfloat16>(g_XL);
    __nv_bfloat16* WqH  = symaddr<__nv_bfloat16>(g_WqH);
    __nv_bfloat16* WqL  = symaddr<__nv_bfloat16>(g_WqL);
    __nv_bfloat16* WkH  = symaddr<__nv_bfloat16>(g_WkH);
    __nv_bfloat16* WkL  = symaddr<__nv_bfloat16>(g_WkL);
    __nv_bfloat16* WvTH = symaddr<__nv_bfloat16>(g_WvTH);
    __nv_bfloat16* WvTL = symaddr<__nv_bfloat16>(g_WvTL);
    __nv_bfloat16* OH   = symaddr<__nv_bfloat16>(g_OH);
    __nv_bfloat16* OL   = symaddr<__nv_bfloat16>(g_OL);
    __nv_bfloat16* GH   = symaddr<__nv_bfloat16>(g_GH);
    __nv_bfloat16* GL   = symaddr<__nv_bfloat16>(g_GL);
    __nv_bfloat16* TH   = symaddr<__nv_bfloat16>(g_TH);
    __nv_bfloat16* TL   = symaddr<__nv_bfloat16>(g_TL);
    __nv_bfloat16* AH   = symaddr<__nv_bfloat16>(g_AH);
    __nv_bfloat16* AL   = symaddr<__nv_bfloat16>(g_AL);
    __nv_bfloat16* SH   = symaddr<__nv_bfloat16>(g_SH);
    __nv_bfloat16* SL   = symaddr<__nv_bfloat16>(g_SL);
    __nv_bfloat16* RtH  = symaddr<__nv_bfloat16>(g_RtH);
    __nv_bfloat16* RtL  = symaddr<__nv_bfloat16>(g_RtL);

    cudaFuncSetAttribute(mma_gemm, cudaFuncAttributeMaxDynamicSharedMemorySize, GEMM_SMEM);

    dim3 tb(32, 8);

    // input/weight conversions (one-time)
    tsplit2_kernel<<<dim3(LO/32, Nn/32, Bb), tb>>>(X, (long)Nn*LO, XtH, XtL, (long)LO*Nn, Nn, LO);
    split2_kernel<<<dim3(2048, Bb), 256>>>(X, (long)Nn*LO, XH, XL, (long)Nn*LO, Nn*LO/2);
    split2_kernel<<<dim3(512, 1), 256>>>(wq, 0, WqH, WqL, 0, LO*LO/2);
    split2_kernel<<<dim3(4096, 1), 256>>>(wk, 0, WkH, WkL, 0, HI*LO/2);
    tsplit2_kernel<<<dim3(LO/32, LO/32, 1), tb>>>(wv, 0, WvTH, WvTL, 0, LO, LO);
    split2_kernel<<<dim3(8192, 1), 256>>>(ow, 0, OH, OL, 0, HI*HI/2);

    // bias correction vectors (exact; zero-valued in this dataset)
    colsum_kernel<<<Bb, LO>>>(X, s);
    rowdot_kernel<<<dim3(LO/8, Bb), 256>>>(wq, s, u, LO, LO, nullptr);
    rowdot_kernel<<<dim3(HI/8, Bb), 256>>>(wk, s, v, HI, LO, nullptr);

    // G_b = Xt Xt^T   [512,512] K=2048  -> hi/lo split epilogue
    mma_gemm<<<dim3(LO/128, LO/128, Bb), 256, GEMM_SMEM>>>(
        Nn, XtH, XtL, (long)LO*Nn, XtH, XtL, (long)LO*Nn,
        nullptr, GH, GL, LO, (long)LO*LO, nullptr, 0);

    // T_b = Wq G_b    (G symmetric => rows of G are K-major)
    mma_gemm<<<dim3(LO/128, LO/128, Bb), 256, GEMM_SMEM>>>(
        LO, WqH, WqL, 0, GH, GL, (long)LO*LO,
        nullptr, TH, TL, LO, (long)LO*LO, nullptr, 0);

    // E_b = T_b Wk^T  [512,4096] K=512  -> fp32 (softmax needs it)
    mma_gemm<<<dim3(HI/128, LO/128, Bb), 256, GEMM_SMEM>>>(
        LO, TH, TL, (long)LO*LO, WkH, WkL, 0,
        E, nullptr, nullptr, HI, (long)LO*HI, nullptr, 0);

    // A_b = softmax(e) + softmax(minmaxnorm(e, mask)) -> hi/lo bf16
    attn_kernel<<<dim3(LO, Bb), 256>>>(E, lk, u, bq, v, bk, AH, AL);

    // bias path: w_b = bv^T A_b ; z_b = w_b O^T + o_b
    wvec_kernel<<<dim3(HI/256, Bb), 256>>>(AH, AL, bv, w);
    rowdot_kernel<<<dim3(HI/8, Bb), 256>>>(ow, w, z, HI, HI, ob);

    // S_b = O A_b^T   [4096,512] K=4096 (dominant) -> hi/lo split epilogue
    mma_gemm<<<dim3(LO/128, HI/128, Bb), 256, GEMM_SMEM>>>(
        HI, OH, OL, 0, AH, AL, (long)LO*HI,
        nullptr, SH, SL, LO, (long)HI*LO, nullptr, 0);

    // Rt_b = S_b Wv   [4096,512] K=512  (Bop = Wv^T)  -> hi/lo split epilogue
    mma_gemm<<<dim3(LO/128, HI/128, Bb), 256, GEMM_SMEM>>>(
        LO, SH, SL, (long)HI*LO, WvTH, WvTL, 0,
        nullptr, RtH, RtL, LO, (long)HI*LO, nullptr, 0);

    // out_b = X_b R_b + z_b  [2048,4096] K=512 (Bop = Rt rows)
    mma_gemm<<<dim3(HI/128, Nn/128, Bb), 256, GEMM_SMEM>>>(
        LO, XH, XL, (long)Nn*LO, RtH, RtL, (long)HI*LO,
        out, nullptr, nullptr, HI, (long)Nn*HI, z, HI);

    (void)in_sizes; (void)n_in; (void)out_size;
}